// round 2
// baseline (speedup 1.0000x reference)
#include <cuda_runtime.h>
#include <cstdint>
#include <cstring>

#define N_NODES 10000
#define N_EDGES 320000
#define IN_DIM  512
#define CH      128

typedef unsigned long long ull;

// ---------------- scratch (__device__ globals; no allocation allowed) ----------------
__device__ int   g_is64;
__device__ int   g_eidx[2 * N_EDGES];
__device__ int   g_deg[N_NODES];
__device__ float g_dinv[N_NODES];
__device__ float g_s0[N_NODES];
__device__ float g_h[N_NODES * CH];
__device__ float g_xw[N_NODES * CH];
__device__ float g_z1[N_NODES * CH];
__device__ float g_W2t[IN_DIM * CH];   // [K][CH]
__device__ float g_Wgt[CH * CH];       // [K][CH]

// ---------------- helpers ----------------
__device__ __forceinline__ ull dup2(float x) {
    float2 t = make_float2(x, x);
    ull r; memcpy(&r, &t, 8); return r;
}
__device__ __forceinline__ float sigf(float x) { return 1.0f / (1.0f + __expf(-x)); }

// ---------------- edge index dtype detection + normalization ----------------
__global__ void k_detect(const void* ei) {
    if (threadIdx.x == 0) {
        const long long* p = (const long long*)ei;
        int ok = 1;
        for (int i = 0; i < 64; i++) {
            long long v = p[i];
            if (v < 0 || v >= N_NODES) ok = 0;
        }
        g_is64 = ok;   // if data were int32, packed pairs would be out of range
    }
}

__global__ void k_edges(const void* ei) {
    int i = blockIdx.x * blockDim.x + threadIdx.x;
    if (i < 2 * N_EDGES) {
        int v = g_is64 ? (int)((const long long*)ei)[i] : ((const int*)ei)[i];
        g_eidx[i] = v;
    }
    if (i < N_NODES) g_deg[i] = 1;  // self-loop
}

__global__ void k_deg() {
    int e = blockIdx.x * blockDim.x + threadIdx.x;
    if (e < N_EDGES) atomicAdd(&g_deg[g_eidx[N_EDGES + e]], 1);
}

__global__ void k_dinv() {
    int i = blockIdx.x * blockDim.x + threadIdx.x;
    if (i < N_NODES) g_dinv[i] = rsqrtf((float)g_deg[i]);
}

// ---------------- weight transpose: W [R][C] -> Wt [C][R] ----------------
__global__ void k_tr(const float* __restrict__ src, float* __restrict__ dst, int R, int C) {
    int idx = blockIdx.x * blockDim.x + threadIdx.x;
    if (idx < R * C) {
        int r = idx / C, c = idx % C;
        dst[c * R + r] = src[idx];
    }
}

// ---------------- GEMM: out[M][128] = A[M][K] @ Wt[K][128] (+bias) ----------------
// BM=64, BN=128, BK=32, 256 threads, TM=8, TN=4, packed f32x2 FMA.
template<int K>
__global__ void __launch_bounds__(256) k_gemm(const float* __restrict__ A,
                                              const float* __restrict__ Wt,
                                              const float* __restrict__ bias,
                                              float* __restrict__ out, int M) {
    __shared__ ull   As2[64][32];     // A tile, each value duplicated into f32x2
    __shared__ float Ws[32][128];     // W tile [k][n]

    int tid = threadIdx.x;
    int tx = tid & 31;      // 32 column groups of 4
    int ty = tid >> 5;      // 8 row groups of 8
    int row0 = blockIdx.x * 64;

    ull acc[8][2];
    #pragma unroll
    for (int i = 0; i < 8; i++) { acc[i][0] = 0ull; acc[i][1] = 0ull; }

    for (int k0 = 0; k0 < K; k0 += 32) {
        // load A tile: 64 rows x 32 k (512 float4 slots)
        #pragma unroll
        for (int i = 0; i < 2; i++) {
            int s = tid + i * 256;
            int m = s >> 3, kq = s & 7;
            int gm = row0 + m;
            float4 v = make_float4(0.f, 0.f, 0.f, 0.f);
            if (gm < M) v = *(const float4*)(A + (size_t)gm * K + k0 + kq * 4);
            ull* dst = &As2[m][kq * 4];
            dst[0] = dup2(v.x); dst[1] = dup2(v.y); dst[2] = dup2(v.z); dst[3] = dup2(v.w);
        }
        // load W tile: 32 k x 128 n (1024 float4 slots)
        #pragma unroll
        for (int i = 0; i < 4; i++) {
            int s = tid + i * 256;
            int kk = s >> 5, nq = s & 31;
            *(float4*)&Ws[kk][nq * 4] = *(const float4*)(Wt + (size_t)(k0 + kk) * CH + nq * 4);
        }
        __syncthreads();

        #pragma unroll
        for (int k = 0; k < 32; k++) {
            float4 bb = *(const float4*)&Ws[k][tx * 4];
            ull b01, b23;
            memcpy(&b01, &bb.x, 8);
            memcpy(&b23, &bb.z, 8);
            #pragma unroll
            for (int i = 0; i < 8; i++) {
                ull aa = As2[ty * 8 + i][k];
                asm("fma.rn.f32x2 %0, %1, %2, %0;" : "+l"(acc[i][0]) : "l"(aa), "l"(b01));
                asm("fma.rn.f32x2 %0, %1, %2, %0;" : "+l"(acc[i][1]) : "l"(aa), "l"(b23));
            }
        }
        __syncthreads();
    }

    float4 bv = make_float4(0.f, 0.f, 0.f, 0.f);
    if (bias) bv = *(const float4*)(bias + tx * 4);
    #pragma unroll
    for (int i = 0; i < 8; i++) {
        int gm = row0 + ty * 8 + i;
        if (gm < M) {
            float2 c01, c23;
            memcpy(&c01, &acc[i][0], 8);
            memcpy(&c23, &acc[i][1], 8);
            float4 o = make_float4(c01.x + bv.x, c01.y + bv.y, c23.x + bv.z, c23.y + bv.w);
            *(float4*)(out + (size_t)gm * CH + tx * 4) = o;
        }
    }
}

// ---------------- row l2-normalize * 1.8 (in place on g_h), warp per row ----------------
__global__ void k_rownorm() {
    int g = blockIdx.x * blockDim.x + threadIdx.x;
    int row = g >> 5, lane = g & 31;
    if (row >= N_NODES) return;
    float4* h4 = (float4*)g_h;
    float4 v = h4[(size_t)row * 32 + lane];
    float ss = v.x * v.x + v.y * v.y + v.z * v.z + v.w * v.w;
    #pragma unroll
    for (int o = 16; o > 0; o >>= 1) ss += __shfl_xor_sync(0xffffffffu, ss, o);
    float s = 1.8f / fmaxf(sqrtf(ss), 1e-12f);
    v.x *= s; v.y *= s; v.z *= s; v.w *= s;
    h4[(size_t)row * 32 + lane] = v;
}

// ---------------- z1 init: z1 = bg + xw * dinv^2 (self-loop term) ----------------
__global__ void k_z1init(const float* __restrict__ bg) {
    int i4 = blockIdx.x * blockDim.x + threadIdx.x;
    if (i4 >= N_NODES * 32) return;
    int n = i4 >> 5, c4 = i4 & 31;
    float d = g_dinv[n];
    float w = d * d;
    float4 xv = ((const float4*)g_xw)[i4];
    float4 b = ((const float4*)bg)[c4];
    ((float4*)g_z1)[i4] = make_float4(b.x + xv.x * w, b.y + xv.y * w,
                                      b.z + xv.z * w, b.w + xv.w * w);
}

// ---------------- edge aggregation: z1[c] += dinv[r]*dinv[c] * xw[r], warp/edge ----------------
__global__ void __launch_bounds__(256) k_agg() {
    int g = blockIdx.x * blockDim.x + threadIdx.x;
    int e = g >> 5, lane = g & 31;
    if (e >= N_EDGES) return;
    int r = g_eidx[e], c = g_eidx[N_EDGES + e];
    float w = g_dinv[r] * g_dinv[c];
    float4 v = ((const float4*)g_xw)[(size_t)r * 32 + lane];
    float* dst = g_z1 + (size_t)c * CH + lane * 4;
    atomicAdd(dst + 0, v.x * w);
    atomicAdd(dst + 1, v.y * w);
    atomicAdd(dst + 2, v.z * w);
    atomicAdd(dst + 3, v.w * w);
}

// ---------------- z2 branch: s0[row] = 0.8 * a / max(||(a,b)||, eps), a=x2row.W22[0] ----------------
#define ZR 16
__global__ void __launch_bounds__(256) k_z2(const float* __restrict__ x2,
                                            const float* __restrict__ W22) {
    __shared__ float4 w0s[1250];
    __shared__ float4 w1s[1250];
    __shared__ float  part[8 * ZR * 2];
    int tid = threadIdx.x;
    int lane = tid & 31, warp = tid >> 5;
    int rbase = blockIdx.x * ZR;

    float a0[ZR], a1[ZR];
    #pragma unroll
    for (int r = 0; r < ZR; r++) { a0[r] = 0.f; a1[r] = 0.f; }

    for (int half = 0; half < 2; half++) {
        int k0 = half * 5000;
        for (int i = tid; i < 1250; i += 256) {
            w0s[i] = *(const float4*)(W22 + k0 + i * 4);
            w1s[i] = *(const float4*)(W22 + N_NODES + k0 + i * 4);
        }
        __syncthreads();
        #pragma unroll
        for (int r = 0; r < ZR; r++) {
            const float4* xr = (const float4*)(x2 + (size_t)(rbase + r) * N_NODES + k0);
            float s0a = 0.f, s1a = 0.f;
            for (int i = tid; i < 1250; i += 256) {
                float4 xv = xr[i];
                float4 wa = w0s[i];
                float4 wb = w1s[i];
                s0a += xv.x * wa.x + xv.y * wa.y + xv.z * wa.z + xv.w * wa.w;
                s1a += xv.x * wb.x + xv.y * wb.y + xv.z * wb.z + xv.w * wb.w;
            }
            a0[r] += s0a; a1[r] += s1a;
        }
        __syncthreads();
    }

    #pragma unroll
    for (int r = 0; r < ZR; r++) {
        #pragma unroll
        for (int o = 16; o > 0; o >>= 1) {
            a0[r] += __shfl_xor_sync(0xffffffffu, a0[r], o);
            a1[r] += __shfl_xor_sync(0xffffffffu, a1[r], o);
        }
    }
    if (lane == 0) {
        #pragma unroll
        for (int r = 0; r < ZR; r++) {
            part[warp * ZR * 2 + r * 2 + 0] = a0[r];
            part[warp * ZR * 2 + r * 2 + 1] = a1[r];
        }
    }
    __syncthreads();
    if (tid < ZR) {
        float a = 0.f, b = 0.f;
        #pragma unroll
        for (int w = 0; w < 8; w++) {
            a += part[w * ZR * 2 + tid * 2 + 0];
            b += part[w * ZR * 2 + tid * 2 + 1];
        }
        g_s0[rbase + tid] = 0.8f * a / fmaxf(sqrtf(a * a + b * b), 1e-12f);
    }
}

// ---------------- final per-edge decoder, warp per edge ----------------
__global__ void __launch_bounds__(256) k_final(float* __restrict__ out) {
    int g = blockIdx.x * blockDim.x + threadIdx.x;
    int e = g >> 5, lane = g & 31;
    if (e >= N_EDGES) return;
    int r = g_eidx[e], c = g_eidx[N_EDGES + e];
    const float4* z4 = (const float4*)g_z1;
    float4 a = z4[(size_t)r * 32 + lane];
    float4 b = z4[(size_t)c * 32 + lane];
    float p = a.x * b.x + a.y * b.y + a.z * b.z + a.w * b.w;
    #pragma unroll
    for (int o = 16; o > 0; o >>= 1) p += __shfl_xor_sync(0xffffffffu, p, o);
    if (lane == 0) {
        float sf = sigf(p);
        float vn = g_s0[r] + g_s0[c];
        out[e] = sf * sf + (1.0f - sf) * sigf(vn);
    }
}

// ---------------- launch ----------------
static void* sym_addr(const void* sym) {
    void* p = nullptr;
    cudaGetSymbolAddress(&p, sym);
    return p;
}

extern "C" void kernel_launch(void* const* d_in, const int* in_sizes, int n_in,
                              void* d_out, int out_size) {
    const float* x   = (const float*)d_in[0];
    const float* x2  = (const float*)d_in[1];
    const float* W2  = (const float*)d_in[2];
    const float* b2  = (const float*)d_in[3];
    const float* Wg  = (const float*)d_in[4];
    const float* bg  = (const float*)d_in[5];
    const float* W22 = (const float*)d_in[6];
    const void*  ei  = d_in[7];
    float* out = (float*)d_out;

    float* p_h   = (float*)sym_addr(g_h);
    float* p_xw  = (float*)sym_addr(g_xw);
    float* p_W2t = (float*)sym_addr(g_W2t);
    float* p_Wgt = (float*)sym_addr(g_Wgt);

    k_detect<<<1, 32>>>(ei);
    k_edges<<<(2 * N_EDGES + 255) / 256, 256>>>(ei);
    k_deg<<<(N_EDGES + 255) / 256, 256>>>();
    k_dinv<<<(N_NODES + 255) / 256, 256>>>();

    k_tr<<<(IN_DIM * CH + 255) / 256, 256>>>(W2, p_W2t, CH, IN_DIM);
    k_tr<<<(CH * CH + 255) / 256, 256>>>(Wg, p_Wgt, CH, CH);

    k_gemm<IN_DIM><<<(N_NODES + 63) / 64, 256>>>(x, p_W2t, b2, p_h, N_NODES);
    k_rownorm<<<(N_NODES * 32 + 255) / 256, 256>>>();
    k_gemm<CH><<<(N_NODES + 63) / 64, 256>>>(p_h, p_Wgt, nullptr, p_xw, N_NODES);

    k_z1init<<<(N_NODES * 32 + 255) / 256, 256>>>(bg);
    k_agg<<<(N_EDGES * 32 + 255) / 256, 256>>>();

    k_z2<<<N_NODES / ZR, 256>>>(x2, W22);

    k_final<<<(N_EDGES * 32 + 255) / 256, 256>>>(out);
}